// round 15
// baseline (speedup 1.0000x reference)
#include <cuda_runtime.h>
#include <cuda_bf16.h>

// AlphaRotatedIoULoss: loss = mean(1 - max(IoU_rot, 1e-6)^3) over N rotated-box pairs.
// Round 14: glue-instruction removal on the Green's-theorem kernel.
//  - safe_inv select chain -> eps-additive reciprocal (antisymmetric, finite)
//  - edge 2/3 negations folded at compile time via edge_contrib<NEG>
//  - copysign shared per antiparallel edge pair; accumulate iou^3, finalize 1-mean.

#define MAX_BLOCKS 16384
static __device__ float g_part[MAX_BLOCKS];
static __device__ unsigned int g_cnt = 0;   // wraps back to 0 every launch

__device__ __forceinline__ float clampf(float v, float lo, float hi) {
    return fminf(fmaxf(v, lo), hi);
}

// Antisymmetric reciprocal without compare/select: for |d| >> 1e-12 the add
// rounds away exactly (below one ulp); at +/-0 gives +/-1e12.
__device__ __forceinline__ float finv(float d) {
    return __fdividef(1.0f, d + copysignf(1e-12f, d));
}

// Contribution of one polygon edge to ∮x dy of the polygon clipped to
// [-W,W]x[-H,H]. All operands describe the UN-negated base edge; NEG=true
// evaluates the antiparallel partner with every sign folded into FFMA/FMUL
// source modifiers at compile time.
//   ix,iy   : reciprocals of the base edge deltas
//   Wix,Hiy : W*ix, H*iy (shared between the edge pair)
//   XH      : copysign(W, dx) of the base edge
//   csy,cvy : this edge's clamped endpoint y's (start, end)
template <bool NEG>
__device__ __forceinline__ float edge_contrib(
    float sx, float sy, float dy, float hdx,
    float ix, float iy, float Wix, float Hiy, float XH,
    float csy, float cvy, float H)
{
    // x-slab crossing interval: t = (+/-W - sx) * (S*ix), S = NEG ? -1 : +1
    float tA, tB, uA, uB;
    if (!NEG) {
        tA = fmaf(sx, -ix, -Wix);
        tB = fmaf(sx, -ix,  Wix);
        uA = fmaf(sy, -iy, -Hiy);
        uB = fmaf(sy, -iy,  Hiy);
    } else {
        tA = fmaf(sx,  ix,  Wix);
        tB = fmaf(sx,  ix, -Wix);
        uA = fmaf(sy,  iy,  Hiy);
        uB = fmaf(sy,  iy, -Hiy);
    }
    float tx0 = clampf(fminf(tA, tB), 0.0f, 1.0f);
    float tx1 = clampf(fmaxf(tA, tB), 0.0f, 1.0f);

    float sdy  = NEG ? -dy  : dy;    // folds into FFMA/FMUL source modifiers
    float shdx = NEG ? -hdx : hdx;

    // y at the x-interval endpoints (boundary-run split points)
    float y0 = fmaf(tx0, sdy, sy);
    float y1 = fmaf(tx1, sdy, sy);

    // interior: y-crossing interval intersected with [tx0, tx1]
    float t0 = clampf(fminf(uA, uB), tx0, tx1);
    float t1 = clampf(fmaxf(uA, uB), tx0, tx1);
    float xm = fmaf(shdx, t0 + t1, sx);
    float interior = sdy * (t1 - t0) * xm;

    // boundary runs at x = -/+ XH_eff; for NEG, XH_eff = -XH and the delta is
    // negated by operand order, so XH * d stays correct.
    float cy0 = clampf(y0, -H, H);
    float cy1 = clampf(y1, -H, H);
    float d = NEG ? ((cy1 - cvy) - (csy - cy0))
                  : ((cvy - cy1) - (cy0 - csy));
    return fmaf(XH, d, interior);
}

// Per-pair iou^3 (loss assembled as 1 - mean at the end).
__device__ __forceinline__ float pair_iou3(
    float x1, float y1, float w1, float h1, float a1,
    float x2, float y2, float w2, float h2, float a2)
{
    float s2f, c2f, s, c;
    __sincosf(a2, &s2f, &c2f);
    __sincosf(a1 - a2, &s, &c);          // relative rotation directly

    // Box1 center in box2's local frame.
    float rx = x1 - x2, ry = y1 - y2;
    float lx =  rx * c2f + ry * s2f;
    float ly = -rx * s2f + ry * c2f;

    float hw1 = 0.5f * w1, hh1 = 0.5f * h1;
    float W = 0.5f * w2,  H = 0.5f * h2;

    float wx = hw1 * c, wy = hw1 * s;
    float hx = -hh1 * s, hy = hh1 * c;

    // Box1 corners (CCW) in box2 frame.
    float kx0 = lx - wx - hx, ky0 = ly - wy - hy;
    float kx1 = lx + wx - hx, ky1 = ly + wy - hy;
    float kx2 = lx + wx + hx, ky2 = ly + wy + hy;
    float kx3 = lx - wx + hx, ky3 = ly - wy + hy;

    // Base edges; central symmetry: edge2 = -edge0, edge3 = -edge1.
    float dx0 = kx1 - kx0, dy0 = ky1 - ky0;
    float dx1 = kx2 - kx1, dy1 = ky2 - ky1;
    float ix0 = finv(dx0), iy0 = finv(dy0);
    float ix1 = finv(dx1), iy1 = finv(dy1);
    float hdx0 = 0.5f * dx0, hdx1 = 0.5f * dx1;

    float Wix0 = W * ix0, Wix1 = W * ix1;
    float Hiy0 = H * iy0, Hiy1 = H * iy1;
    float XH0 = copysignf(W, dx0);
    float XH1 = copysignf(W, dx1);

    // Clamped corner y's (boundary-run endpoints).
    float cy0 = clampf(ky0, -H, H);
    float cy1 = clampf(ky1, -H, H);
    float cy2 = clampf(ky2, -H, H);
    float cy3 = clampf(ky3, -H, H);

    float acc;
    acc  = edge_contrib<false>(kx0, ky0, dy0, hdx0, ix0, iy0, Wix0, Hiy0, XH0, cy0, cy1, H);
    acc += edge_contrib<false>(kx1, ky1, dy1, hdx1, ix1, iy1, Wix1, Hiy1, XH1, cy1, cy2, H);
    acc += edge_contrib<true >(kx2, ky2, dy0, hdx0, ix0, iy0, Wix0, Hiy0, XH0, cy2, cy3, H);
    acc += edge_contrib<true >(kx3, ky3, dy1, hdx1, ix1, iy1, Wix1, Hiy1, XH1, cy3, cy0, H);

    float inter = fabsf(acc);            // CCW -> acc >= 0
    float area1 = w1 * h1;
    float area2 = w2 * h2;
    float iou = __fdividef(inter, area1 + area2 - inter);
    iou = fmaxf(iou, 1e-6f);
    return iou * iou * iou;
}

__global__ __launch_bounds__(256) void arl_fused_kernel(
    const float* __restrict__ pred,
    const float* __restrict__ tgt,
    float* __restrict__ out,
    int n, float inv_n)
{
    int tid = threadIdx.x;
    int gid = blockIdx.x * 256 + tid;
    int i0 = gid * 2;                    // this thread owns pairs i0, i0+1
    float val = 0.0f;                    // sum of iou^3

    if (i0 + 1 < n) {
        // 80B per tensor per thread; base allocator-aligned, offset 8B-aligned.
        const float2* p2 = reinterpret_cast<const float2*>(pred + 10 * gid);
        const float2* t2 = reinterpret_cast<const float2*>(tgt + 10 * gid);
        float2 pa = __ldg(p2 + 0), pb = __ldg(p2 + 1), pc = __ldg(p2 + 2),
               pd = __ldg(p2 + 3), pe = __ldg(p2 + 4);
        float2 ta = __ldg(t2 + 0), tb = __ldg(t2 + 1), tc = __ldg(t2 + 2),
               td = __ldg(t2 + 3), te = __ldg(t2 + 4);

        float vA = pair_iou3(pa.x, pa.y, pb.x, pb.y, pc.x,
                             ta.x, ta.y, tb.x, tb.y, tc.x);
        float vB = pair_iou3(pc.y, pd.x, pd.y, pe.x, pe.y,
                             tc.y, td.x, td.y, te.x, te.y);
        val = vA + vB;
    } else if (i0 < n) {
        const float* p = pred + 5 * i0;
        const float* t = tgt + 5 * i0;
        val = pair_iou3(__ldg(p + 0), __ldg(p + 1), __ldg(p + 2),
                        __ldg(p + 3), __ldg(p + 4),
                        __ldg(t + 0), __ldg(t + 1), __ldg(t + 2),
                        __ldg(t + 3), __ldg(t + 4));
    }

    // Block reduction.
    __shared__ float wsum[8];
    __shared__ bool s_last;
    #pragma unroll
    for (int off = 16; off > 0; off >>= 1)
        val += __shfl_down_sync(0xffffffffu, val, off);
    int lane = tid & 31;
    int wid  = tid >> 5;
    if (lane == 0) wsum[wid] = val;
    __syncthreads();
    if (wid == 0) {
        float v = (lane < 8) ? wsum[lane] : 0.0f;
        #pragma unroll
        for (int off = 4; off > 0; off >>= 1)
            v += __shfl_down_sync(0xffu, v, off);
        if (lane == 0) {
            g_part[blockIdx.x] = v;
            __threadfence();
            // atomicInc wraps to 0 after gridDim.x increments -> counter ends
            // every launch at 0 (graph-replay deterministic).
            unsigned int old = atomicInc(&g_cnt, gridDim.x - 1);
            s_last = (old == gridDim.x - 1);
        }
    }
    __syncthreads();

    // Last block reduces the per-block partials and writes the mean loss.
    if (s_last) {
        double v = 0.0;
        for (int j = tid; j < gridDim.x; j += 256)
            v += (double)g_part[j];
        #pragma unroll
        for (int off = 16; off > 0; off >>= 1)
            v += __shfl_down_sync(0xffffffffu, v, off);
        __shared__ double dsum[8];
        if (lane == 0) dsum[wid] = v;
        __syncthreads();
        if (wid == 0) {
            double d = (lane < 8) ? dsum[lane] : 0.0;
            #pragma unroll
            for (int off = 4; off > 0; off >>= 1)
                d += __shfl_down_sync(0xffu, d, off);
            if (lane == 0)
                out[0] = (float)(1.0 - d * (double)inv_n);   // mean(1 - iou^3)
        }
    }
}

extern "C" void kernel_launch(void* const* d_in, const int* in_sizes, int n_in,
                              void* d_out, int out_size)
{
    const float* pred = (const float*)d_in[0];
    const float* tgt  = (const float*)d_in[1];
    float* out = (float*)d_out;
    int n = in_sizes[0] / 5;

    int pairs_per_block = 512;           // 256 threads x 2 pairs
    int blocks = (n + pairs_per_block - 1) / pairs_per_block;
    if (blocks > MAX_BLOCKS) blocks = MAX_BLOCKS;   // N=1e6 -> 1954, fits
    arl_fused_kernel<<<blocks, 256>>>(pred, tgt, out, n, 1.0f / (float)n);
}

// round 16
// speedup vs baseline: 1.0680x; 1.0680x over previous
#include <cuda_runtime.h>
#include <cuda_bf16.h>

// AlphaRotatedIoULoss: loss = mean(1 - max(IoU_rot, 1e-6)^3) over N rotated-box pairs.
// Round 16: FOUR pairs per thread -> 80B/tensor/thread is 16B-aligned -> 5x
// LDG.128 per tensor (halves load-instruction front, halves L1tex queue
// pressure vs 2-pair float2 version). Compute body identical to R14 (rel_err 0).

#define MAX_BLOCKS 16384
static __device__ float g_part[MAX_BLOCKS];
static __device__ unsigned int g_cnt = 0;   // wraps back to 0 every launch

__device__ __forceinline__ float clampf(float v, float lo, float hi) {
    return fminf(fmaxf(v, lo), hi);
}

// Antisymmetric reciprocal without compare/select: for |d| >> 1e-12 the add
// rounds away exactly (below one ulp); at +/-0 gives +/-1e12.
__device__ __forceinline__ float finv(float d) {
    return __fdividef(1.0f, d + copysignf(1e-12f, d));
}

// Contribution of one polygon edge to ∮x dy of the polygon clipped to
// [-W,W]x[-H,H]; NEG=true evaluates the antiparallel partner with all signs
// folded into source modifiers at compile time.
template <bool NEG>
__device__ __forceinline__ float edge_contrib(
    float sx, float sy, float dy, float hdx,
    float ix, float iy, float Wix, float Hiy, float XH,
    float csy, float cvy, float H)
{
    float tA, tB, uA, uB;
    if (!NEG) {
        tA = fmaf(sx, -ix, -Wix);
        tB = fmaf(sx, -ix,  Wix);
        uA = fmaf(sy, -iy, -Hiy);
        uB = fmaf(sy, -iy,  Hiy);
    } else {
        tA = fmaf(sx,  ix,  Wix);
        tB = fmaf(sx,  ix, -Wix);
        uA = fmaf(sy,  iy,  Hiy);
        uB = fmaf(sy,  iy, -Hiy);
    }
    float tx0 = clampf(fminf(tA, tB), 0.0f, 1.0f);
    float tx1 = clampf(fmaxf(tA, tB), 0.0f, 1.0f);

    float sdy  = NEG ? -dy  : dy;
    float shdx = NEG ? -hdx : hdx;

    float y0 = fmaf(tx0, sdy, sy);
    float y1 = fmaf(tx1, sdy, sy);

    float t0 = clampf(fminf(uA, uB), tx0, tx1);
    float t1 = clampf(fmaxf(uA, uB), tx0, tx1);
    float xm = fmaf(shdx, t0 + t1, sx);
    float interior = sdy * (t1 - t0) * xm;

    float cy0 = clampf(y0, -H, H);
    float cy1 = clampf(y1, -H, H);
    float d = NEG ? ((cy1 - cvy) - (csy - cy0))
                  : ((cvy - cy1) - (cy0 - csy));
    return fmaf(XH, d, interior);
}

// Per-pair iou^3 (loss assembled as 1 - mean at the end).
__device__ __forceinline__ float pair_iou3(
    float x1, float y1, float w1, float h1, float a1,
    float x2, float y2, float w2, float h2, float a2)
{
    float s2f, c2f, s, c;
    __sincosf(a2, &s2f, &c2f);
    __sincosf(a1 - a2, &s, &c);

    float rx = x1 - x2, ry = y1 - y2;
    float lx =  rx * c2f + ry * s2f;
    float ly = -rx * s2f + ry * c2f;

    float hw1 = 0.5f * w1, hh1 = 0.5f * h1;
    float W = 0.5f * w2,  H = 0.5f * h2;

    float wx = hw1 * c, wy = hw1 * s;
    float hx = -hh1 * s, hy = hh1 * c;

    float kx0 = lx - wx - hx, ky0 = ly - wy - hy;
    float kx1 = lx + wx - hx, ky1 = ly + wy - hy;
    float kx2 = lx + wx + hx, ky2 = ly + wy + hy;
    float kx3 = lx - wx + hx, ky3 = ly - wy + hy;

    float dx0 = kx1 - kx0, dy0 = ky1 - ky0;
    float dx1 = kx2 - kx1, dy1 = ky2 - ky1;
    float ix0 = finv(dx0), iy0 = finv(dy0);
    float ix1 = finv(dx1), iy1 = finv(dy1);
    float hdx0 = 0.5f * dx0, hdx1 = 0.5f * dx1;

    float Wix0 = W * ix0, Wix1 = W * ix1;
    float Hiy0 = H * iy0, Hiy1 = H * iy1;
    float XH0 = copysignf(W, dx0);
    float XH1 = copysignf(W, dx1);

    float cy0 = clampf(ky0, -H, H);
    float cy1 = clampf(ky1, -H, H);
    float cy2 = clampf(ky2, -H, H);
    float cy3 = clampf(ky3, -H, H);

    float acc;
    acc  = edge_contrib<false>(kx0, ky0, dy0, hdx0, ix0, iy0, Wix0, Hiy0, XH0, cy0, cy1, H);
    acc += edge_contrib<false>(kx1, ky1, dy1, hdx1, ix1, iy1, Wix1, Hiy1, XH1, cy1, cy2, H);
    acc += edge_contrib<true >(kx2, ky2, dy0, hdx0, ix0, iy0, Wix0, Hiy0, XH0, cy2, cy3, H);
    acc += edge_contrib<true >(kx3, ky3, dy1, hdx1, ix1, iy1, Wix1, Hiy1, XH1, cy3, cy0, H);

    float inter = fabsf(acc);
    float area1 = w1 * h1;
    float area2 = w2 * h2;
    float iou = __fdividef(inter, area1 + area2 - inter);
    iou = fmaxf(iou, 1e-6f);
    return iou * iou * iou;
}

__global__ __launch_bounds__(256) void arl_fused_kernel(
    const float* __restrict__ pred,
    const float* __restrict__ tgt,
    float* __restrict__ out,
    int n, float inv_n)
{
    int tid = threadIdx.x;
    int gid = blockIdx.x * 256 + tid;
    int i0 = gid * 4;                    // this thread owns pairs i0..i0+3
    float val = 0.0f;                    // sum of iou^3

    if (i0 + 4 <= n) {
        // 160B per tensor per thread at float offset 20*gid: 20*gid*4 = 80*gid
        // bytes -> 16B-aligned -> 5x LDG.128 per tensor.
        const float4* p4 = reinterpret_cast<const float4*>(pred + 20 * gid);
        const float4* t4 = reinterpret_cast<const float4*>(tgt + 20 * gid);
        float4 pa = __ldg(p4 + 0), pb = __ldg(p4 + 1), pc = __ldg(p4 + 2),
               pd = __ldg(p4 + 3), pe = __ldg(p4 + 4);
        float4 ta = __ldg(t4 + 0), tb = __ldg(t4 + 1), tc = __ldg(t4 + 2),
               td = __ldg(t4 + 3), te = __ldg(t4 + 4);

        // Pair 0: floats 0-4, pair 1: 5-9, pair 2: 10-14, pair 3: 15-19.
        val  = pair_iou3(pa.x, pa.y, pa.z, pa.w, pb.x,
                         ta.x, ta.y, ta.z, ta.w, tb.x);
        val += pair_iou3(pb.y, pb.z, pb.w, pc.x, pc.y,
                         tb.y, tb.z, tb.w, tc.x, tc.y);
        val += pair_iou3(pc.z, pc.w, pd.x, pd.y, pd.z,
                         tc.z, tc.w, td.x, td.y, td.z);
        val += pair_iou3(pd.w, pe.x, pe.y, pe.z, pe.w,
                         td.w, te.x, te.y, te.z, te.w);
    } else {
        #pragma unroll
        for (int q = 0; q < 4; q++) {
            int i = i0 + q;
            if (i < n) {
                const float* p = pred + 5 * i;
                const float* t = tgt + 5 * i;
                val += pair_iou3(__ldg(p + 0), __ldg(p + 1), __ldg(p + 2),
                                 __ldg(p + 3), __ldg(p + 4),
                                 __ldg(t + 0), __ldg(t + 1), __ldg(t + 2),
                                 __ldg(t + 3), __ldg(t + 4));
            }
        }
    }

    // Block reduction.
    __shared__ float wsum[8];
    __shared__ bool s_last;
    #pragma unroll
    for (int off = 16; off > 0; off >>= 1)
        val += __shfl_down_sync(0xffffffffu, val, off);
    int lane = tid & 31;
    int wid  = tid >> 5;
    if (lane == 0) wsum[wid] = val;
    __syncthreads();
    if (wid == 0) {
        float v = (lane < 8) ? wsum[lane] : 0.0f;
        #pragma unroll
        for (int off = 4; off > 0; off >>= 1)
            v += __shfl_down_sync(0xffu, v, off);
        if (lane == 0) {
            g_part[blockIdx.x] = v;
            __threadfence();
            // atomicInc wraps to 0 after gridDim.x increments -> counter ends
            // every launch at 0 (graph-replay deterministic).
            unsigned int old = atomicInc(&g_cnt, gridDim.x - 1);
            s_last = (old == gridDim.x - 1);
        }
    }
    __syncthreads();

    // Last block reduces the per-block partials and writes the mean loss.
    if (s_last) {
        double v = 0.0;
        for (int j = tid; j < gridDim.x; j += 256)
            v += (double)g_part[j];
        #pragma unroll
        for (int off = 16; off > 0; off >>= 1)
            v += __shfl_down_sync(0xffffffffu, v, off);
        __shared__ double dsum[8];
        if (lane == 0) dsum[wid] = v;
        __syncthreads();
        if (wid == 0) {
            double d = (lane < 8) ? dsum[lane] : 0.0;
            #pragma unroll
            for (int off = 4; off > 0; off >>= 1)
                d += __shfl_down_sync(0xffu, d, off);
            if (lane == 0)
                out[0] = (float)(1.0 - d * (double)inv_n);   // mean(1 - iou^3)
        }
    }
}

extern "C" void kernel_launch(void* const* d_in, const int* in_sizes, int n_in,
                              void* d_out, int out_size)
{
    const float* pred = (const float*)d_in[0];
    const float* tgt  = (const float*)d_in[1];
    float* out = (float*)d_out;
    int n = in_sizes[0] / 5;

    int pairs_per_block = 1024;          // 256 threads x 4 pairs
    int blocks = (n + pairs_per_block - 1) / pairs_per_block;
    if (blocks > MAX_BLOCKS) blocks = MAX_BLOCKS;   // N=1e6 -> 977, fits
    arl_fused_kernel<<<blocks, 256>>>(pred, tgt, out, n, 1.0f / (float)n);
}